// round 2
// baseline (speedup 1.0000x reference)
#include <cuda_runtime.h>
#include <cstdint>

#define NPTS    6890
#define BF      (NPTS * 3)          // 20670 floats per batch per tensor
#define THREADS 512
#define NWARPS  (THREADS / 32)

// smem layout (float offsets). 20672 floats = 82688 B per tensor buffer
// (2 floats of leading alignment slack + round-up).
#define SM_PRED 0
#define SM_GT   20672
#define SM_RED  41344               // NWARPS * 16 = 256 floats
#define SM_STAT 41600               // 16 floats
#define SM_PRM  41616               // 12 floats used (R*scale 9, t 3)
#define SM_MBAR 41632               // 8 bytes, 8B aligned (41632*4 % 8 == 0)
#define SMEM_FLOATS (41632 + 4)
#define SMEM_BYTES  (SMEM_FLOATS * 4)

#define TMA_BYTES 82688u            // (20670 + 2) * 4, multiple of 16

__device__ __forceinline__ uint32_t smem_addr(const void* p) {
    return (uint32_t)__cvta_generic_to_shared(p);
}

__device__ __forceinline__ void accum_pt(float* a,
                                         float p0, float p1, float p2,
                                         float g0, float g1, float g2) {
    a[0] += p0; a[1] += p1; a[2] += p2;
    a[3] += g0; a[4] += g1; a[5] += g2;
    a[6] = fmaf(p0, p0, fmaf(p1, p1, fmaf(p2, p2, a[6])));
    a[7]  = fmaf(p0, g0, a[7]);
    a[8]  = fmaf(p0, g1, a[8]);
    a[9]  = fmaf(p0, g2, a[9]);
    a[10] = fmaf(p1, g0, a[10]);
    a[11] = fmaf(p1, g1, a[11]);
    a[12] = fmaf(p1, g2, a[12]);
    a[13] = fmaf(p2, g0, a[13]);
    a[14] = fmaf(p2, g1, a[14]);
    a[15] = fmaf(p2, g2, a[15]);
}

__global__ void __launch_bounds__(THREADS, 1)
procrustes_l1_kernel(const float* __restrict__ pred,
                     const float* __restrict__ gt,
                     float* __restrict__ out) {
    extern __shared__ float sm[];
    float* predS = sm + SM_PRED;
    float* gtS   = sm + SM_GT;
    float* redS  = sm + SM_RED;
    float* statS = sm + SM_STAT;
    float* prm   = sm + SM_PRM;

    const int tid = threadIdx.x;
    const size_t gbase = (size_t)blockIdx.x * BF;
    const int pad = (int)(gbase & 3);   // 0 (even batch) or 2 (odd batch)

    const uint32_t mbarA = smem_addr(sm + SM_MBAR);

    if (tid == 0) {
        asm volatile("mbarrier.init.shared.b64 [%0], 1;" :: "r"(mbarA) : "memory");
    }
    __syncthreads();

    // --- TMA bulk load: pred + gt batch into smem (aligned-down by pad) ---
    if (tid == 0) {
        asm volatile("mbarrier.arrive.expect_tx.shared.b64 _, [%0], %1;"
                     :: "r"(mbarA), "r"(2u * TMA_BYTES) : "memory");
        uint32_t dp = smem_addr(predS);
        uint32_t dg = smem_addr(gtS);
        const float* srcP = pred + (gbase - (size_t)pad);
        const float* srcG = gt   + (gbase - (size_t)pad);
        asm volatile("cp.async.bulk.shared::cluster.global.mbarrier::complete_tx::bytes [%0], [%1], %2, [%3];"
                     :: "r"(dp), "l"(srcP), "r"(TMA_BYTES), "r"(mbarA) : "memory");
        asm volatile("cp.async.bulk.shared::cluster.global.mbarrier::complete_tx::bytes [%0], [%1], %2, [%3];"
                     :: "r"(dg), "l"(srcG), "r"(TMA_BYTES), "r"(mbarA) : "memory");
    }
    // all threads wait (acquire)
    {
        uint32_t done = 0;
        while (!done) {
            asm volatile("{\n\t.reg .pred p;\n\t"
                         "mbarrier.try_wait.parity.acquire.cta.shared::cta.b64 p, [%1], %2, 0x989680;\n\t"
                         "selp.b32 %0, 1, 0, p;\n\t}"
                         : "=r"(done) : "r"(mbarA), "r"(0u) : "memory");
        }
    }

    // --- Pass A: 16-value reduction over N points (pairs of points = 3 float2 each) ---
    float acc[16];
#pragma unroll
    for (int i = 0; i < 16; i++) acc[i] = 0.f;

    const float* pS = predS + pad;
    const float* gS = gtS + pad;
    for (int j = tid; j < NPTS / 2; j += THREADS) {
        int base = 6 * j;
        float2 pa = *(const float2*)(pS + base);
        float2 pb = *(const float2*)(pS + base + 2);
        float2 pc = *(const float2*)(pS + base + 4);
        float2 ga = *(const float2*)(gS + base);
        float2 gb = *(const float2*)(gS + base + 2);
        float2 gc = *(const float2*)(gS + base + 4);
        accum_pt(acc, pa.x, pa.y, pb.x, ga.x, ga.y, gb.x);
        accum_pt(acc, pb.y, pc.x, pc.y, gb.y, gc.x, gc.y);
    }

    // warp reduce
#pragma unroll
    for (int i = 0; i < 16; i++) {
        float v = acc[i];
        v += __shfl_down_sync(0xffffffffu, v, 16);
        v += __shfl_down_sync(0xffffffffu, v, 8);
        v += __shfl_down_sync(0xffffffffu, v, 4);
        v += __shfl_down_sync(0xffffffffu, v, 2);
        v += __shfl_down_sync(0xffffffffu, v, 1);
        acc[i] = v;
    }
    const int lane = tid & 31;
    const int wp = tid >> 5;
    if (lane == 0) {
#pragma unroll
        for (int i = 0; i < 16; i++) redS[wp * 16 + i] = acc[i];
    }
    __syncthreads();
    if (tid < 16) {
        float s = redS[tid];
#pragma unroll
        for (int w = 1; w < NWARPS; w++) s += redS[w * 16 + tid];
        statS[tid] = s;
    }
    __syncthreads();

    // --- Thread 0: 3x3 Procrustes solve (fp32 Jacobi on K^T K) ---
    if (tid == 0) {
        const float fN = (float)NPTS;
        float sp[3] = { statS[0], statS[1], statS[2] };
        float sg[3] = { statS[3], statS[4], statS[5] };
        float spp = statS[6];
        float mu1[3], mu2[3];
#pragma unroll
        for (int i = 0; i < 3; i++) { mu1[i] = sp[i] / fN; mu2[i] = sg[i] / fN; }

        float K[3][3];
#pragma unroll
        for (int i = 0; i < 3; i++)
#pragma unroll
            for (int j = 0; j < 3; j++)
                K[i][j] = statS[7 + 3 * i + j] - fN * mu1[i] * mu2[j] + 1e-8f;

        float var1 = spp - fN * (mu1[0] * mu1[0] + mu1[1] * mu1[1] + mu1[2] * mu1[2]);

        // A = K^T K (symmetric)
        float A[3][3];
#pragma unroll
        for (int i = 0; i < 3; i++)
#pragma unroll
            for (int j = 0; j < 3; j++)
                A[i][j] = K[0][i] * K[0][j] + K[1][i] * K[1][j] + K[2][i] * K[2][j];

        float V[3][3] = { {1.f,0.f,0.f}, {0.f,1.f,0.f}, {0.f,0.f,1.f} };

        // cyclic Jacobi, 6 sweeps
        for (int sweep = 0; sweep < 6; sweep++) {
#pragma unroll
            for (int pair = 0; pair < 3; pair++) {
                int p = (pair == 2) ? 1 : 0;
                int q = (pair == 0) ? 1 : 2;
                float apq = A[p][q];
                if (fabsf(apq) > 1e-18f) {
                    float app = A[p][p], aqq = A[q][q];
                    float tau = (aqq - app) / (2.f * apq);
                    float tt = copysignf(1.f, tau) / (fabsf(tau) + sqrtf(1.f + tau * tau));
                    float c = rsqrtf(1.f + tt * tt);
                    float s = tt * c;
#pragma unroll
                    for (int k = 0; k < 3; k++) {   // A <- A * G
                        float akp = A[k][p], akq = A[k][q];
                        A[k][p] = c * akp - s * akq;
                        A[k][q] = s * akp + c * akq;
                    }
#pragma unroll
                    for (int k = 0; k < 3; k++) {   // A <- G^T * A
                        float apk = A[p][k], aqk = A[q][k];
                        A[p][k] = c * apk - s * aqk;
                        A[q][k] = s * apk + c * aqk;
                    }
#pragma unroll
                    for (int k = 0; k < 3; k++) {   // V <- V * G
                        float vkp = V[k][p], vkq = V[k][q];
                        V[k][p] = c * vkp - s * vkq;
                        V[k][q] = s * vkp + c * vkq;
                    }
                }
            }
        }

        // sort eigenvalues descending
        float dd[3] = { A[0][0], A[1][1], A[2][2] };
        int oo[3] = { 0, 1, 2 };
        if (dd[oo[0]] < dd[oo[1]]) { int t = oo[0]; oo[0] = oo[1]; oo[1] = t; }
        if (dd[oo[0]] < dd[oo[2]]) { int t = oo[0]; oo[0] = oo[2]; oo[2] = t; }
        if (dd[oo[1]] < dd[oo[2]]) { int t = oo[1]; oo[1] = oo[2]; oo[2] = t; }

        float v0[3], v1[3], v2[3];
#pragma unroll
        for (int i = 0; i < 3; i++) {
            v0[i] = V[i][oo[0]];
            v1[i] = V[i][oo[1]];
            v2[i] = V[i][oo[2]];
        }
        // force det(V) = +1 (flip 3rd column if needed)
        float det =
            v0[0] * (v1[1] * v2[2] - v1[2] * v2[1]) -
            v0[1] * (v1[0] * v2[2] - v1[2] * v2[0]) +
            v0[2] * (v1[0] * v2[1] - v1[1] * v2[0]);
        if (det < 0.f) { v2[0] = -v2[0]; v2[1] = -v2[1]; v2[2] = -v2[2]; }

        float Kv0[3], Kv1[3];
#pragma unroll
        for (int i = 0; i < 3; i++) {
            Kv0[i] = K[i][0] * v0[0] + K[i][1] * v0[1] + K[i][2] * v0[2];
            Kv1[i] = K[i][0] * v1[0] + K[i][1] * v1[1] + K[i][2] * v1[2];
        }
        float r0 = rsqrtf(Kv0[0] * Kv0[0] + Kv0[1] * Kv0[1] + Kv0[2] * Kv0[2] + 1e-30f);
        float u0[3] = { Kv0[0] * r0, Kv0[1] * r0, Kv0[2] * r0 };
        float d01 = u0[0] * Kv1[0] + u0[1] * Kv1[1] + u0[2] * Kv1[2];
        float u1r[3] = { Kv1[0] - d01 * u0[0], Kv1[1] - d01 * u0[1], Kv1[2] - d01 * u0[2] };
        float r1 = rsqrtf(u1r[0] * u1r[0] + u1r[1] * u1r[1] + u1r[2] * u1r[2] + 1e-30f);
        float u1[3] = { u1r[0] * r1, u1r[1] * r1, u1r[2] * r1 };
        float w[3] = { u0[1] * u1[2] - u0[2] * u1[1],
                       u0[2] * u1[0] - u0[0] * u1[2],
                       u0[0] * u1[1] - u0[1] * u1[0] };

        // R = v0 u0^T + v1 u1^T + v2 w^T  (w absorbs the reflection sign)
        float R[3][3];
#pragma unroll
        for (int i = 0; i < 3; i++)
#pragma unroll
            for (int j = 0; j < 3; j++)
                R[i][j] = v0[i] * u0[j] + v1[i] * u1[j] + v2[i] * w[j];

        // trace(R K) computed directly (robust)
        float tr = 0.f;
#pragma unroll
        for (int i = 0; i < 3; i++)
#pragma unroll
            for (int j = 0; j < 3; j++)
                tr += R[i][j] * K[j][i];
        float scale = tr / var1;

        // fold scale into R, compute t
#pragma unroll
        for (int i = 0; i < 3; i++)
#pragma unroll
            for (int j = 0; j < 3; j++)
                R[i][j] *= scale;
#pragma unroll
        for (int i = 0; i < 3; i++)
            prm[9 + i] = mu2[i] - (R[i][0] * mu1[0] + R[i][1] * mu1[1] + R[i][2] * mu1[2]);
#pragma unroll
        for (int i = 0; i < 3; i++)
#pragma unroll
            for (int j = 0; j < 3; j++)
                prm[3 * i + j] = R[i][j];
    }
    __syncthreads();

    // --- Pass B: out = |Rs*p + t - g|, written in-place into predS ---
    float Rs[9], tv[3];
#pragma unroll
    for (int i = 0; i < 9; i++) Rs[i] = prm[i];
    tv[0] = prm[9]; tv[1] = prm[10]; tv[2] = prm[11];

    float* pW = predS + pad;
    for (int j = tid; j < NPTS / 2; j += THREADS) {
        int base = 6 * j;
        float2 pa = *(const float2*)(pW + base);
        float2 pb = *(const float2*)(pW + base + 2);
        float2 pc = *(const float2*)(pW + base + 4);
        float2 ga = *(const float2*)(gS + base);
        float2 gb = *(const float2*)(gS + base + 2);
        float2 gc = *(const float2*)(gS + base + 4);

        float p0x = pa.x, p0y = pa.y, p0z = pb.x;
        float p1x = pb.y, p1y = pc.x, p1z = pc.y;

        float o0x = fabsf(fmaf(Rs[0], p0x, fmaf(Rs[1], p0y, fmaf(Rs[2], p0z, tv[0]))) - ga.x);
        float o0y = fabsf(fmaf(Rs[3], p0x, fmaf(Rs[4], p0y, fmaf(Rs[5], p0z, tv[1]))) - ga.y);
        float o0z = fabsf(fmaf(Rs[6], p0x, fmaf(Rs[7], p0y, fmaf(Rs[8], p0z, tv[2]))) - gb.x);
        float o1x = fabsf(fmaf(Rs[0], p1x, fmaf(Rs[1], p1y, fmaf(Rs[2], p1z, tv[0]))) - gb.y);
        float o1y = fabsf(fmaf(Rs[3], p1x, fmaf(Rs[4], p1y, fmaf(Rs[5], p1z, tv[1]))) - gc.x);
        float o1z = fabsf(fmaf(Rs[6], p1x, fmaf(Rs[7], p1y, fmaf(Rs[8], p1z, tv[2]))) - gc.y);

        *(float2*)(pW + base)     = make_float2(o0x, o0y);
        *(float2*)(pW + base + 2) = make_float2(o0z, o1x);
        *(float2*)(pW + base + 4) = make_float2(o1y, o1z);
    }
    __syncthreads();

    // --- Store: TMA bulk interior (16B aligned both sides) + 2 scalar edge elems ---
    if (tid == 0) {
        asm volatile("fence.proxy.async.shared::cta;" ::: "memory");
        uint32_t src = smem_addr(predS + 2 * pad);     // smem slot of element e=pad
        float* dst = out + gbase + (size_t)pad;        // 16B aligned
        asm volatile("cp.async.bulk.global.shared::cta.bulk_group [%0], [%1], %2;"
                     :: "l"(dst), "r"(src), "r"(20668u * 4u) : "memory");
        asm volatile("cp.async.bulk.commit_group;" ::: "memory");
        if (pad) {
            out[gbase]     = predS[pad];       // element 0
            out[gbase + 1] = predS[pad + 1];   // element 1
        } else {
            out[gbase + 20668] = predS[20668];
            out[gbase + 20669] = predS[20669];
        }
        asm volatile("cp.async.bulk.wait_group 0;" ::: "memory");
    }
}

extern "C" void kernel_launch(void* const* d_in, const int* in_sizes, int n_in,
                              void* d_out, int out_size) {
    const float* pred = (const float*)d_in[0];
    const float* gt   = (const float*)d_in[1];
    float* out = (float*)d_out;
    int B = in_sizes[0] / BF;   // 1024

    cudaFuncSetAttribute(procrustes_l1_kernel,
                         cudaFuncAttributeMaxDynamicSharedMemorySize, SMEM_BYTES);
    procrustes_l1_kernel<<<B, THREADS, SMEM_BYTES>>>(pred, gt, out);
}